// round 2
// baseline (speedup 1.0000x reference)
#include <cuda_runtime.h>

#define Bn 128
#define Ln 1024
#define INF_ 136
#define F1 256
#define F2 512
#define Hn 256
#define G4 1024

// ---- scratch (device globals) ----
__device__ float g_W1T[INF_ * F1];
__device__ float g_W2T[F1 * F2];
__device__ float g_WihT0[F2 * G4];
__device__ float g_WihT1[Hn * G4];
__device__ float g_WihT2[Hn * G4];
__device__ float g_bsum0[G4];
__device__ float g_bsum1[G4];
__device__ float g_bsum2[G4];
__device__ float g_feat[(size_t)Ln * Bn * F2];
__device__ float g_xg[(size_t)Ln * Bn * G4];
__device__ float g_hA[(size_t)Ln * Bn * Hn];
__device__ float g_hB[(size_t)Ln * Bn * Hn];
__device__ float g_hstate[2][Hn * Bn];
__device__ unsigned g_barctr;

__global__ void transpose_kernel(const float* __restrict__ in, float* __restrict__ out,
                                 int rows, int cols) {
    int i = blockIdx.x * blockDim.x + threadIdx.x;
    if (i < rows * cols) {
        int r = i / cols, c = i % cols;
        out[c * rows + r] = in[i];
    }
}

__global__ void addbias_kernel(const float* __restrict__ a, const float* __restrict__ b,
                               float* __restrict__ out, int n) {
    int i = blockIdx.x * blockDim.x + threadIdx.x;
    if (i < n) out[i] = a[i] + b[i];
}

__global__ void reset_kernel() {
    int i = blockIdx.x * blockDim.x + threadIdx.x;
    if (i == 0) g_barctr = 0u;
    if (i < Hn * Bn) g_hstate[0][i] = 0.f;
}

// ---- MLP: feat[t][b][512] = relu(relu(x@W1^T+b1)@W2^T+b2), 16 rows/block ----
__global__ __launch_bounds__(256) void mlp_kernel(const float* __restrict__ x,
                                                  const float* __restrict__ b1,
                                                  const float* __restrict__ b2) {
    __shared__ float xs[16 * INF_];
    __shared__ float h1s[16 * F1];
    const int tid = threadIdx.x;
    const size_t row0 = (size_t)blockIdx.x * 16;

    const float* xr = x + row0 * INF_;
    for (int i = tid; i < 16 * INF_; i += 256) xs[i] = xr[i];
    __syncthreads();

    {
        float acc[16];
        const float bb = b1[tid];
#pragma unroll
        for (int r = 0; r < 16; ++r) acc[r] = bb;
#pragma unroll 4
        for (int k = 0; k < INF_; ++k) {
            float w = g_W1T[k * F1 + tid];
#pragma unroll
            for (int r = 0; r < 16; ++r) acc[r] = fmaf(xs[r * INF_ + k], w, acc[r]);
        }
#pragma unroll
        for (int r = 0; r < 16; ++r) h1s[r * F1 + tid] = fmaxf(acc[r], 0.f);
    }
    __syncthreads();

    {
        float acc0[16], acc1[16];
        const float bb0 = b2[tid], bb1 = b2[tid + 256];
#pragma unroll
        for (int r = 0; r < 16; ++r) { acc0[r] = bb0; acc1[r] = bb1; }
#pragma unroll 2
        for (int k = 0; k < F1; ++k) {
            float w0 = g_W2T[k * F2 + tid];
            float w1 = g_W2T[k * F2 + tid + 256];
#pragma unroll
            for (int r = 0; r < 16; ++r) {
                float a = h1s[r * F1 + k];
                acc0[r] = fmaf(a, w0, acc0[r]);
                acc1[r] = fmaf(a, w1, acc1[r]);
            }
        }
#pragma unroll
        for (int r = 0; r < 16; ++r) {
            size_t row = row0 + r;
            int b_ = (int)(row / Ln), t_ = (int)(row % Ln);
            float* fp = g_feat + ((size_t)t_ * Bn + b_) * F2;
            fp[tid] = fmaxf(acc0[r], 0.f);
            fp[tid + 256] = fmaxf(acc1[r], 0.f);
        }
    }
}

// ---- gate-input projection: out[row][0..1023] = A[row]@WT + bsum, rows = t*B+b ----
template <int K>
__global__ __launch_bounds__(256) void xg_kernel(const float* __restrict__ A,
                                                 const float* __restrict__ WT,
                                                 const float* __restrict__ bsum,
                                                 float* __restrict__ out) {
    extern __shared__ float As[];  // [16][K]
    const int tid = threadIdx.x;
    const size_t row0 = (size_t)blockIdx.x * 16;
    const float* ap = A + row0 * K;
    for (int i = tid; i < 16 * K; i += 256) As[i] = ap[i];
    __syncthreads();

    float acc[16][4];
    float bb[4];
#pragma unroll
    for (int j = 0; j < 4; ++j) bb[j] = bsum[tid + j * 256];
#pragma unroll
    for (int r = 0; r < 16; ++r)
#pragma unroll
        for (int j = 0; j < 4; ++j) acc[r][j] = bb[j];

    const float* wp = WT + tid;
#pragma unroll 2
    for (int k = 0; k < K; ++k) {
        float w0 = wp[(size_t)k * G4];
        float w1 = wp[(size_t)k * G4 + 256];
        float w2 = wp[(size_t)k * G4 + 512];
        float w3 = wp[(size_t)k * G4 + 768];
#pragma unroll
        for (int r = 0; r < 16; ++r) {
            float a = As[r * K + k];
            acc[r][0] = fmaf(a, w0, acc[r][0]);
            acc[r][1] = fmaf(a, w1, acc[r][1]);
            acc[r][2] = fmaf(a, w2, acc[r][2]);
            acc[r][3] = fmaf(a, w3, acc[r][3]);
        }
    }
#pragma unroll
    for (int r = 0; r < 16; ++r) {
        float* op = out + (row0 + r) * G4;
        op[tid] = acc[r][0];
        op[tid + 256] = acc[r][1];
        op[tid + 512] = acc[r][2];
        op[tid + 768] = acc[r][3];
    }
}

// ---- LSTM recurrence, one layer: 128 co-resident blocks, grid barrier per step ----
__global__ __launch_bounds__(256) void lstm_rec_kernel(const float* __restrict__ xg,
                                                       const float* __restrict__ w_hh,
                                                       float* __restrict__ hout) {
    extern __shared__ float sm[];
    float* w_s = sm;               // [256][32]
    float* h_s = sm + Hn * 32;     // [256][32]
    float* gx  = sm + 2 * Hn * 32; // [32][33]

    const int tid = threadIdx.x;
    const int bid = blockIdx.x;
    const int ubase = (bid & 31) * 8;
    const int rbase = (bid >> 5) * 32;

    const int cl = tid & 31;
    const int rq = tid >> 5;
    const int gsel = cl >> 3;
    const int uu = cl & 7;
    const int jcol = gsel * Hn + ubase + uu;

    for (int k = rq; k < Hn; k += 8) w_s[k * 32 + cl] = w_hh[jcol * Hn + k];

    const int pu = tid & 7;
    const int pr = tid >> 3;
    float cst = 0.f;
    const unsigned nb = gridDim.x;

    __syncthreads();

    for (int t = 0; t < Ln; ++t) {
        const float* hrd = g_hstate[t & 1];
        float* hwr = g_hstate[(t + 1) & 1];

        for (int idx = tid; idx < Hn * 32; idx += 256) {
            int k = idx >> 5, r = idx & 31;
            h_s[idx] = hrd[k * Bn + rbase + r];
        }
        __syncthreads();

        const float* xp = xg + ((size_t)t * Bn + rbase + rq * 4) * G4 + jcol;
        float a0 = xp[0];
        float a1 = xp[G4];
        float a2 = xp[2 * G4];
        float a3 = xp[3 * G4];
        const float4* hp = reinterpret_cast<const float4*>(h_s) + rq;
        const float* wp = w_s + cl;
#pragma unroll 8
        for (int k = 0; k < Hn; ++k) {
            float4 h4 = hp[k * 8];
            float w = wp[k * 32];
            a0 = fmaf(h4.x, w, a0);
            a1 = fmaf(h4.y, w, a1);
            a2 = fmaf(h4.z, w, a2);
            a3 = fmaf(h4.w, w, a3);
        }
        float* gp = gx + cl * 33 + rq * 4;
        gp[0] = a0; gp[1] = a1; gp[2] = a2; gp[3] = a3;
        __syncthreads();

        float iv = gx[(0 * 8 + pu) * 33 + pr];
        float fv = gx[(1 * 8 + pu) * 33 + pr];
        float gv = gx[(2 * 8 + pu) * 33 + pr];
        float ov = gx[(3 * 8 + pu) * 33 + pr];
        iv = 1.f / (1.f + expf(-iv));
        fv = 1.f / (1.f + expf(-fv));
        gv = tanhf(gv);
        ov = 1.f / (1.f + expf(-ov));
        cst = fv * cst + iv * gv;
        float hv = ov * tanhf(cst);
        hwr[(ubase + pu) * Bn + rbase + pr] = hv;
        hout[((size_t)t * Bn + rbase + pr) * Hn + ubase + pu] = hv;

        __syncthreads();
        if (tid == 0) {
            __threadfence();
            atomicAdd(&g_barctr, 1u);
            const unsigned target = (unsigned)(t + 1) * nb;
            volatile unsigned* ctr = (volatile unsigned*)&g_barctr;
            while (*ctr < target) __nanosleep(64);
            __threadfence();
        }
        __syncthreads();
    }
}

// ---- decision head + ragged mean ----
__global__ __launch_bounds__(256) void decision_kernel(const float* __restrict__ hseq,
                                                       const float* __restrict__ Wd,
                                                       const float* __restrict__ bd,
                                                       const int* __restrict__ length,
                                                       float* __restrict__ out) {
    const int b = blockIdx.x;
    const int tid = threadIdx.x;
    const int len = length[b];
    const float w = Wd[tid];
    float s0 = 0.f, s1 = 0.f, s2 = 0.f, s3 = 0.f;
    int t = 0;
    for (; t + 4 <= len; t += 4) {
        s0 = fmaf(hseq[((size_t)(t + 0) * Bn + b) * Hn + tid], w, s0);
        s1 = fmaf(hseq[((size_t)(t + 1) * Bn + b) * Hn + tid], w, s1);
        s2 = fmaf(hseq[((size_t)(t + 2) * Bn + b) * Hn + tid], w, s2);
        s3 = fmaf(hseq[((size_t)(t + 3) * Bn + b) * Hn + tid], w, s3);
    }
    for (; t < len; ++t) s0 = fmaf(hseq[((size_t)t * Bn + b) * Hn + tid], w, s0);
    float s = (s0 + s1) + (s2 + s3);
    __shared__ float red[256];
    red[tid] = s;
    __syncthreads();
    for (int st = 128; st > 0; st >>= 1) {
        if (tid < st) red[tid] += red[tid + st];
        __syncthreads();
    }
    if (tid == 0) out[b] = red[0] / (float)len + bd[0];
}

extern "C" void kernel_launch(void* const* d_in, const int* in_sizes, int n_in,
                              void* d_out, int out_size) {
    const float* x     = (const float*)d_in[0];
    const int* length  = (const int*)d_in[1];
    const float* W1    = (const float*)d_in[2];
    const float* b1    = (const float*)d_in[3];
    const float* W2    = (const float*)d_in[4];
    const float* b2    = (const float*)d_in[5];
    const float* w_ih0 = (const float*)d_in[6];
    const float* w_hh0 = (const float*)d_in[7];
    const float* b_ih0 = (const float*)d_in[8];
    const float* b_hh0 = (const float*)d_in[9];
    const float* w_ih1 = (const float*)d_in[10];
    const float* w_hh1 = (const float*)d_in[11];
    const float* b_ih1 = (const float*)d_in[12];
    const float* b_hh1 = (const float*)d_in[13];
    const float* w_ih2 = (const float*)d_in[14];
    const float* w_hh2 = (const float*)d_in[15];
    const float* b_ih2 = (const float*)d_in[16];
    const float* b_hh2 = (const float*)d_in[17];
    const float* Wd    = (const float*)d_in[18];
    const float* bd    = (const float*)d_in[19];
    float* out = (float*)d_out;

    float *dW1T, *dW2T, *dT0, *dT1, *dT2, *dB0, *dB1, *dB2;
    float *dFeat, *dXg, *dHA, *dHB;
    cudaGetSymbolAddress((void**)&dW1T, g_W1T);
    cudaGetSymbolAddress((void**)&dW2T, g_W2T);
    cudaGetSymbolAddress((void**)&dT0, g_WihT0);
    cudaGetSymbolAddress((void**)&dT1, g_WihT1);
    cudaGetSymbolAddress((void**)&dT2, g_WihT2);
    cudaGetSymbolAddress((void**)&dB0, g_bsum0);
    cudaGetSymbolAddress((void**)&dB1, g_bsum1);
    cudaGetSymbolAddress((void**)&dB2, g_bsum2);
    cudaGetSymbolAddress((void**)&dFeat, g_feat);
    cudaGetSymbolAddress((void**)&dXg, g_xg);
    cudaGetSymbolAddress((void**)&dHA, g_hA);
    cudaGetSymbolAddress((void**)&dHB, g_hB);

    static int smem_set = 0;
    if (!smem_set) {
        cudaFuncSetAttribute(lstm_rec_kernel, cudaFuncAttributeMaxDynamicSharedMemorySize,
                             (2 * Hn * 32 + 32 * 33) * sizeof(float));
        smem_set = 1;
    }

    // weight prep
    transpose_kernel<<<(F1 * INF_ + 255) / 256, 256>>>(W1, dW1T, F1, INF_);
    transpose_kernel<<<(F2 * F1 + 255) / 256, 256>>>(W2, dW2T, F2, F1);
    transpose_kernel<<<(G4 * F2 + 255) / 256, 256>>>(w_ih0, dT0, G4, F2);
    transpose_kernel<<<(G4 * Hn + 255) / 256, 256>>>(w_ih1, dT1, G4, Hn);
    transpose_kernel<<<(G4 * Hn + 255) / 256, 256>>>(w_ih2, dT2, G4, Hn);
    addbias_kernel<<<4, 256>>>(b_ih0, b_hh0, dB0, G4);
    addbias_kernel<<<4, 256>>>(b_ih1, b_hh1, dB1, G4);
    addbias_kernel<<<4, 256>>>(b_ih2, b_hh2, dB2, G4);

    const int nrows = Bn * Ln;
    mlp_kernel<<<nrows / 16, 256>>>(x, b1, b2);

    const int lstm_smem = (2 * Hn * 32 + 32 * 33) * sizeof(float);

    // layer 0
    xg_kernel<F2><<<nrows / 16, 256, 16 * F2 * sizeof(float)>>>(dFeat, dT0, dB0, dXg);
    reset_kernel<<<128, 256>>>();
    lstm_rec_kernel<<<128, 256, lstm_smem>>>(dXg, w_hh0, dHA);
    // layer 1
    xg_kernel<Hn><<<nrows / 16, 256, 16 * Hn * sizeof(float)>>>(dHA, dT1, dB1, dXg);
    reset_kernel<<<128, 256>>>();
    lstm_rec_kernel<<<128, 256, lstm_smem>>>(dXg, w_hh1, dHB);
    // layer 2
    xg_kernel<Hn><<<nrows / 16, 256, 16 * Hn * sizeof(float)>>>(dHB, dT2, dB2, dXg);
    reset_kernel<<<128, 256>>>();
    lstm_rec_kernel<<<128, 256, lstm_smem>>>(dXg, w_hh2, dHA);

    decision_kernel<<<Bn, 256>>>(dHA, Wd, bd, length, out);
}

// round 3
// speedup vs baseline: 1.2947x; 1.2947x over previous
#include <cuda_runtime.h>

#define Bn 128
#define Ln 1024
#define INF_ 136
#define F1 256
#define F2 512
#define Hn 256
#define G4 1024

// ---- scratch (device globals) ----
__device__ float g_W1T[INF_ * F1];
__device__ float g_W2T[F1 * F2];
__device__ float g_W4_0[(size_t)F2 * G4];   // packed [k][256][4]
__device__ float g_W4_1[(size_t)Hn * G4];
__device__ float g_W4_2[(size_t)Hn * G4];
__device__ float g_bsum0[G4];
__device__ float g_bsum1[G4];
__device__ float g_bsum2[G4];
__device__ float g_feat[(size_t)Ln * Bn * F2];   // [t][b][512]
__device__ float g_xg[(size_t)Ln * Bn * G4];     // [t*B+b][1024]
__device__ float g_hA[(size_t)Ln * Bn * Hn];
__device__ float g_hB[(size_t)Ln * Bn * Hn];
__device__ float g_hstate[2][Hn * Bn];           // [u][b] ping-pong
__device__ unsigned g_grpctr[4 * 32];            // 4 counters, 128B apart

// ---- f32x2 packed FMA helpers ----
union F2U { float2 f; unsigned long long u; };

__device__ __forceinline__ float2 ffma2(float2 a, float2 b, float2 c) {
    F2U A, B, C, D;
    A.f = a; B.f = b; C.f = c;
    asm("fma.rn.f32x2 %0, %1, %2, %3;" : "=l"(D.u) : "l"(A.u), "l"(B.u), "l"(C.u));
    return D.f;
}

// ---- prep kernels ----
__global__ void transpose_kernel(const float* __restrict__ in, float* __restrict__ out,
                                 int rows, int cols) {
    int i = blockIdx.x * blockDim.x + threadIdx.x;
    if (i < rows * cols) {
        int r = i / cols, c = i % cols;
        out[c * rows + r] = in[i];
    }
}

// pack w_ih [1024][K] -> out[(k*256 + c)*4 + g] = W[(g*256+c)*K + k]
__global__ void pack_w4_kernel(const float* __restrict__ W, float* __restrict__ out, int K) {
    int i = blockIdx.x * blockDim.x + threadIdx.x;
    if (i < K * G4) {
        int k = i >> 10;
        int rem = i & 1023;
        int c = rem >> 2;
        int g = rem & 3;
        out[i] = W[(size_t)(g * 256 + c) * K + k];
    }
}

__global__ void addbias_kernel(const float* __restrict__ a, const float* __restrict__ b,
                               float* __restrict__ out, int n) {
    int i = blockIdx.x * blockDim.x + threadIdx.x;
    if (i < n) out[i] = a[i] + b[i];
}

__global__ void reset_kernel() {
    int i = blockIdx.x * blockDim.x + threadIdx.x;
    if (i < 128) g_grpctr[i] = 0u;
    if (i < Hn * Bn) g_hstate[0][i] = 0.f;
}

// ---- MLP: feat[t][b][512] = relu(relu(x@W1^T+b1)@W2^T+b2), 16 rows/block ----
__global__ __launch_bounds__(256) void mlp_kernel(const float* __restrict__ x,
                                                  const float* __restrict__ b1,
                                                  const float* __restrict__ b2) {
    __shared__ float xs[16 * INF_];
    __shared__ float h1s[16 * F1];
    const int tid = threadIdx.x;
    const size_t row0 = (size_t)blockIdx.x * 16;

    const float* xr = x + row0 * INF_;
    for (int i = tid; i < 16 * INF_; i += 256) xs[i] = xr[i];
    __syncthreads();

    {
        float acc[16];
        const float bb = b1[tid];
#pragma unroll
        for (int r = 0; r < 16; ++r) acc[r] = bb;
#pragma unroll 4
        for (int k = 0; k < INF_; ++k) {
            float w = g_W1T[k * F1 + tid];
#pragma unroll
            for (int r = 0; r < 16; ++r) acc[r] = fmaf(xs[r * INF_ + k], w, acc[r]);
        }
#pragma unroll
        for (int r = 0; r < 16; ++r) h1s[r * F1 + tid] = fmaxf(acc[r], 0.f);
    }
    __syncthreads();

    {
        float acc0[16], acc1[16];
        const float bb0 = b2[tid], bb1 = b2[tid + 256];
#pragma unroll
        for (int r = 0; r < 16; ++r) { acc0[r] = bb0; acc1[r] = bb1; }
#pragma unroll 2
        for (int k = 0; k < F1; ++k) {
            float w0 = g_W2T[k * F2 + tid];
            float w1 = g_W2T[k * F2 + tid + 256];
#pragma unroll
            for (int r = 0; r < 16; ++r) {
                float a = h1s[r * F1 + k];
                acc0[r] = fmaf(a, w0, acc0[r]);
                acc1[r] = fmaf(a, w1, acc1[r]);
            }
        }
#pragma unroll
        for (int r = 0; r < 16; ++r) {
            size_t row = row0 + r;
            int b_ = (int)(row / Ln), t_ = (int)(row % Ln);
            float* fp = g_feat + ((size_t)t_ * Bn + b_) * F2;
            fp[tid] = fmaxf(acc0[r], 0.f);
            fp[tid + 256] = fmaxf(acc1[r], 0.f);
        }
    }
}

// ---- xg GEMM v2: 32 rows/block, f32x2, k-major smem A, packed W4 ----
// SRC_KMAJOR: A is [t][256][128] (K==256); else A is [(t*128+b)][K] row-major.
template <int K, bool SRC_KMAJOR>
__global__ __launch_bounds__(256, 1) void xg2_kernel(const float* __restrict__ A,
                                                     const float* __restrict__ W4,
                                                     const float* __restrict__ bsum,
                                                     float* __restrict__ out) {
    extern __shared__ float As[];  // [K][36]
    const int tid = threadIdx.x;
    const int row0 = blockIdx.x * 32;

    if (SRC_KMAJOR) {
        const int t = row0 >> 7, b0 = row0 & 127;
        const float* base = A + ((size_t)t * K) * 128 + b0;
        for (int i = tid; i < K * 8; i += 256) {
            int k = i >> 3, r4 = (i & 7) * 4;
            *(float4*)(As + k * 36 + r4) = *(const float4*)(base + (size_t)k * 128 + r4);
        }
    } else {
        constexpr int KQ = K / 4;
        for (int i = tid; i < 32 * KQ; i += 256) {
            int r = i / KQ, kq = i % KQ;
            float4 v = *(const float4*)(A + (size_t)(row0 + r) * K + kq * 4);
            As[(kq * 4 + 0) * 36 + r] = v.x;
            As[(kq * 4 + 1) * 36 + r] = v.y;
            As[(kq * 4 + 2) * 36 + r] = v.z;
            As[(kq * 4 + 3) * 36 + r] = v.w;
        }
    }
    __syncthreads();

    float2 acc[16][4];
#pragma unroll
    for (int p = 0; p < 16; ++p)
#pragma unroll
        for (int g = 0; g < 4; ++g) acc[p][g] = make_float2(0.f, 0.f);

    const float4* wp = (const float4*)W4 + tid;
#pragma unroll 2
    for (int k = 0; k < K; ++k) {
        float4 w4 = wp[(size_t)k * 256];
        float2 w2[4];
        w2[0] = make_float2(w4.x, w4.x);
        w2[1] = make_float2(w4.y, w4.y);
        w2[2] = make_float2(w4.z, w4.z);
        w2[3] = make_float2(w4.w, w4.w);
        const float4* ap = (const float4*)(As + k * 36);
#pragma unroll
        for (int q = 0; q < 8; ++q) {
            float4 a4 = ap[q];
            float2 alo = make_float2(a4.x, a4.y);
            float2 ahi = make_float2(a4.z, a4.w);
#pragma unroll
            for (int g = 0; g < 4; ++g) {
                acc[2 * q][g]     = ffma2(alo, w2[g], acc[2 * q][g]);
                acc[2 * q + 1][g] = ffma2(ahi, w2[g], acc[2 * q + 1][g]);
            }
        }
    }

    float bb[4];
#pragma unroll
    for (int g = 0; g < 4; ++g) bb[g] = bsum[tid + g * 256];
#pragma unroll
    for (int p = 0; p < 16; ++p) {
        float* o0 = out + (size_t)(row0 + 2 * p) * G4 + tid;
        float* o1 = o0 + G4;
#pragma unroll
        for (int g = 0; g < 4; ++g) {
            o0[g * 256] = acc[p][g].x + bb[g];
            o1[g * 256] = acc[p][g].y + bb[g];
        }
    }
}

// ---- LSTM recurrence: 128 blocks, f32x2, 4 independent group barriers ----
// OUT_TBU: hout[t][b][u] (for decision); else hout[t][u][b] (for next xg).
template <bool OUT_TBU>
__global__ __launch_bounds__(256) void lstm2_kernel(const float* __restrict__ xg,
                                                    const float* __restrict__ w_hh,
                                                    float* __restrict__ hout) {
    extern __shared__ float sm[];
    float* w_s = sm;                 // [256][32]
    float* h_s = sm + Hn * 32;       // [256][32]
    float* gx  = sm + 2 * Hn * 32;   // [32][36]

    const int tid = threadIdx.x;
    const int bid = blockIdx.x;
    const int ubase = (bid & 31) * 8;
    const int rbase = (bid >> 5) * 32;
    const int grp = bid >> 5;

    const int cl = tid & 31;
    const int rq = tid >> 5;
    const int gsel = cl >> 3;
    const int uu = cl & 7;
    const int jcol = gsel * Hn + ubase + uu;

    for (int k = rq; k < Hn; k += 8) w_s[k * 32 + cl] = w_hh[(size_t)jcol * Hn + k];

    const int pu = tid >> 5;    // unit 0..7
    const int pr = tid & 31;    // row 0..31 (lane-consecutive)
    float cst = 0.f;
    unsigned* ctr = &g_grpctr[grp * 32];

    __syncthreads();

    for (int t = 0; t < Ln; ++t) {
        // xg operand loads first — latency hidden under the FMA loop
        const float* xp = xg + ((size_t)t * Bn + rbase + rq * 4) * G4 + jcol;
        float x0 = xp[0];
        float x1 = xp[G4];
        float x2 = xp[2 * G4];
        float x3 = xp[3 * G4];

        const float* hrd = g_hstate[t & 1];
        float* hwr = g_hstate[(t + 1) & 1];
        for (int i = tid; i < Hn * 8; i += 256) {
            int k = i >> 3, r4 = (i & 7) * 4;
            *(float4*)(h_s + k * 32 + r4) = *(const float4*)(hrd + k * Bn + rbase + r4);
        }
        __syncthreads();

        float2 a01 = make_float2(0.f, 0.f);
        float2 a23 = make_float2(0.f, 0.f);
        const float* hp = h_s + rq * 4;
        const float* wc = w_s + cl;
#pragma unroll 8
        for (int k = 0; k < Hn; ++k) {
            float4 h4 = *(const float4*)(hp + k * 32);
            float w = wc[k * 32];
            float2 w2 = make_float2(w, w);
            a01 = ffma2(make_float2(h4.x, h4.y), w2, a01);
            a23 = ffma2(make_float2(h4.z, h4.w), w2, a23);
        }
        a01.x += x0; a01.y += x1; a23.x += x2; a23.y += x3;
        *(float4*)(gx + cl * 36 + rq * 4) = make_float4(a01.x, a01.y, a23.x, a23.y);
        __syncthreads();

        float iv = gx[(0 * 8 + pu) * 36 + pr];
        float fv = gx[(1 * 8 + pu) * 36 + pr];
        float gv = gx[(2 * 8 + pu) * 36 + pr];
        float ov = gx[(3 * 8 + pu) * 36 + pr];
        iv = 1.f / (1.f + expf(-iv));
        fv = 1.f / (1.f + expf(-fv));
        gv = tanhf(gv);
        ov = 1.f / (1.f + expf(-ov));
        cst = fv * cst + iv * gv;
        float hv = ov * tanhf(cst);
        hwr[(ubase + pu) * Bn + rbase + pr] = hv;
        if (OUT_TBU)
            hout[((size_t)t * Bn + rbase + pr) * Hn + ubase + pu] = hv;
        else
            hout[((size_t)t * Hn + ubase + pu) * Bn + rbase + pr] = hv;

        __syncthreads();
        if (tid == 0) {
            asm volatile("red.release.gpu.global.add.u32 [%0], %1;" :: "l"(ctr), "r"(1u) : "memory");
            const unsigned target = (unsigned)(t + 1) * 32u;
            unsigned v;
            do {
                asm volatile("ld.acquire.gpu.global.u32 %0, [%1];" : "=r"(v) : "l"(ctr) : "memory");
                if (v >= target) break;
                __nanosleep(32);
            } while (true);
        }
        __syncthreads();
    }
}

// ---- decision head + ragged mean (hseq is [t][b][u]) ----
__global__ __launch_bounds__(256) void decision_kernel(const float* __restrict__ hseq,
                                                       const float* __restrict__ Wd,
                                                       const float* __restrict__ bd,
                                                       const int* __restrict__ length,
                                                       float* __restrict__ out) {
    const int b = blockIdx.x;
    const int tid = threadIdx.x;
    const int len = length[b];
    const float w = Wd[tid];
    float s0 = 0.f, s1 = 0.f, s2 = 0.f, s3 = 0.f;
    int t = 0;
    for (; t + 4 <= len; t += 4) {
        s0 = fmaf(hseq[((size_t)(t + 0) * Bn + b) * Hn + tid], w, s0);
        s1 = fmaf(hseq[((size_t)(t + 1) * Bn + b) * Hn + tid], w, s1);
        s2 = fmaf(hseq[((size_t)(t + 2) * Bn + b) * Hn + tid], w, s2);
        s3 = fmaf(hseq[((size_t)(t + 3) * Bn + b) * Hn + tid], w, s3);
    }
    for (; t < len; ++t) s0 = fmaf(hseq[((size_t)t * Bn + b) * Hn + tid], w, s0);
    float s = (s0 + s1) + (s2 + s3);
    __shared__ float red[256];
    red[tid] = s;
    __syncthreads();
    for (int st = 128; st > 0; st >>= 1) {
        if (tid < st) red[tid] += red[tid + st];
        __syncthreads();
    }
    if (tid == 0) out[b] = red[0] / (float)len + bd[0];
}

extern "C" void kernel_launch(void* const* d_in, const int* in_sizes, int n_in,
                              void* d_out, int out_size) {
    const float* x     = (const float*)d_in[0];
    const int* length  = (const int*)d_in[1];
    const float* W1    = (const float*)d_in[2];
    const float* b1    = (const float*)d_in[3];
    const float* W2    = (const float*)d_in[4];
    const float* b2    = (const float*)d_in[5];
    const float* w_ih0 = (const float*)d_in[6];
    const float* w_hh0 = (const float*)d_in[7];
    const float* b_ih0 = (const float*)d_in[8];
    const float* b_hh0 = (const float*)d_in[9];
    const float* w_ih1 = (const float*)d_in[10];
    const float* w_hh1 = (const float*)d_in[11];
    const float* b_ih1 = (const float*)d_in[12];
    const float* b_hh1 = (const float*)d_in[13];
    const float* w_ih2 = (const float*)d_in[14];
    const float* w_hh2 = (const float*)d_in[15];
    const float* b_ih2 = (const float*)d_in[16];
    const float* b_hh2 = (const float*)d_in[17];
    const float* Wd    = (const float*)d_in[18];
    const float* bd    = (const float*)d_in[19];
    float* out = (float*)d_out;

    float *dW1T, *dW2T, *dP0, *dP1, *dP2, *dB0, *dB1, *dB2;
    float *dFeat, *dXg, *dHA, *dHB;
    cudaGetSymbolAddress((void**)&dW1T, g_W1T);
    cudaGetSymbolAddress((void**)&dW2T, g_W2T);
    cudaGetSymbolAddress((void**)&dP0, g_W4_0);
    cudaGetSymbolAddress((void**)&dP1, g_W4_1);
    cudaGetSymbolAddress((void**)&dP2, g_W4_2);
    cudaGetSymbolAddress((void**)&dB0, g_bsum0);
    cudaGetSymbolAddress((void**)&dB1, g_bsum1);
    cudaGetSymbolAddress((void**)&dB2, g_bsum2);
    cudaGetSymbolAddress((void**)&dFeat, g_feat);
    cudaGetSymbolAddress((void**)&dXg, g_xg);
    cudaGetSymbolAddress((void**)&dHA, g_hA);
    cudaGetSymbolAddress((void**)&dHB, g_hB);

    const int xg_smem512 = 512 * 36 * sizeof(float);
    const int xg_smem256 = 256 * 36 * sizeof(float);
    const int lstm_smem = (2 * Hn * 32 + 32 * 36) * sizeof(float);
    cudaFuncSetAttribute(xg2_kernel<F2, false>, cudaFuncAttributeMaxDynamicSharedMemorySize, xg_smem512);
    cudaFuncSetAttribute(xg2_kernel<Hn, true>, cudaFuncAttributeMaxDynamicSharedMemorySize, xg_smem256);
    cudaFuncSetAttribute(lstm2_kernel<false>, cudaFuncAttributeMaxDynamicSharedMemorySize, lstm_smem);
    cudaFuncSetAttribute(lstm2_kernel<true>, cudaFuncAttributeMaxDynamicSharedMemorySize, lstm_smem);

    // weight prep
    transpose_kernel<<<(F1 * INF_ + 255) / 256, 256>>>(W1, dW1T, F1, INF_);
    transpose_kernel<<<(F2 * F1 + 255) / 256, 256>>>(W2, dW2T, F2, F1);
    pack_w4_kernel<<<(F2 * G4 + 255) / 256, 256>>>(w_ih0, dP0, F2);
    pack_w4_kernel<<<(Hn * G4 + 255) / 256, 256>>>(w_ih1, dP1, Hn);
    pack_w4_kernel<<<(Hn * G4 + 255) / 256, 256>>>(w_ih2, dP2, Hn);
    addbias_kernel<<<4, 256>>>(b_ih0, b_hh0, dB0, G4);
    addbias_kernel<<<4, 256>>>(b_ih1, b_hh1, dB1, G4);
    addbias_kernel<<<4, 256>>>(b_ih2, b_hh2, dB2, G4);

    const int nrows = Bn * Ln;
    mlp_kernel<<<nrows / 16, 256>>>(x, b1, b2);

    // layer 0: feat row-major -> xg -> lstm writes [t][u][b]
    xg2_kernel<F2, false><<<nrows / 32, 256, xg_smem512>>>(dFeat, dP0, dB0, dXg);
    reset_kernel<<<128, 256>>>();
    lstm2_kernel<false><<<128, 256, lstm_smem>>>(dXg, w_hh0, dHA);
    // layer 1: hA [t][u][b] k-major -> xg -> lstm writes [t][u][b]
    xg2_kernel<Hn, true><<<nrows / 32, 256, xg_smem256>>>(dHA, dP1, dB1, dXg);
    reset_kernel<<<128, 256>>>();
    lstm2_kernel<false><<<128, 256, lstm_smem>>>(dXg, w_hh1, dHB);
    // layer 2: final layer writes [t][b][u] for decision head
    xg2_kernel<Hn, true><<<nrows / 32, 256, xg_smem256>>>(dHB, dP2, dB2, dXg);
    reset_kernel<<<128, 256>>>();
    lstm2_kernel<true><<<128, 256, lstm_smem>>>(dXg, w_hh2, dHA);

    decision_kernel<<<Bn, 256>>>(dHA, Wd, bd, length, out);
}

// round 4
// speedup vs baseline: 1.5085x; 1.1652x over previous
#include <cuda_runtime.h>

#define Bn 128
#define Ln 1024
#define INF_ 136
#define F1 256
#define F2 512
#define Hn 256
#define G4 1024

// ---- scratch (device globals) ----
__device__ float g_W1T[INF_ * F1];
__device__ float g_W2T[F1 * F2];
__device__ float g_W4_0[(size_t)F2 * G4];   // packed [k][256][4]
__device__ float g_W4_1[(size_t)Hn * G4];
__device__ float g_W4_2[(size_t)Hn * G4];
__device__ float g_bsum0[G4];
__device__ float g_bsum1[G4];
__device__ float g_bsum2[G4];
__device__ float g_feat[(size_t)Ln * Bn * F2];   // [t][b][512]
__device__ float g_xg[(size_t)Ln * Bn * G4];     // [t*B+b][1024]
__device__ float g_hA[(size_t)Ln * Bn * Hn];
__device__ float g_hB[(size_t)Ln * Bn * Hn];
__device__ float g_hstate[2][Hn * Bn];           // [u][b] ping-pong
__device__ unsigned g_grpctr[4 * 32];            // 4 counters, 128B apart

// ---- f32x2 packed FMA ----
union F2U { float2 f; unsigned long long u; };
__device__ __forceinline__ float2 ffma2(float2 a, float2 b, float2 c) {
    F2U A, B, C, D;
    A.f = a; B.f = b; C.f = c;
    asm("fma.rn.f32x2 %0, %1, %2, %3;" : "=l"(D.u) : "l"(A.u), "l"(B.u), "l"(C.u));
    return D.f;
}

// ---- prep kernels ----
__global__ void transpose_kernel(const float* __restrict__ in, float* __restrict__ out,
                                 int rows, int cols) {
    int i = blockIdx.x * blockDim.x + threadIdx.x;
    if (i < rows * cols) {
        int r = i / cols, c = i % cols;
        out[c * rows + r] = in[i];
    }
}

__global__ void pack_w4_kernel(const float* __restrict__ W, float* __restrict__ out, int K) {
    int i = blockIdx.x * blockDim.x + threadIdx.x;
    if (i < K * G4) {
        int k = i >> 10;
        int rem = i & 1023;
        int c = rem >> 2;
        int g = rem & 3;
        out[i] = W[(size_t)(g * 256 + c) * K + k];
    }
}

__global__ void addbias_kernel(const float* __restrict__ a, const float* __restrict__ b,
                               float* __restrict__ out, int n) {
    int i = blockIdx.x * blockDim.x + threadIdx.x;
    if (i < n) out[i] = a[i] + b[i];
}

__global__ void reset_kernel() {
    int i = blockIdx.x * blockDim.x + threadIdx.x;
    if (i < 128) g_grpctr[i] = 0u;
    if (i < Hn * Bn) g_hstate[0][i] = 0.f;
}

// ---- MLP (unchanged) ----
__global__ __launch_bounds__(256) void mlp_kernel(const float* __restrict__ x,
                                                  const float* __restrict__ b1,
                                                  const float* __restrict__ b2) {
    __shared__ float xs[16 * INF_];
    __shared__ float h1s[16 * F1];
    const int tid = threadIdx.x;
    const size_t row0 = (size_t)blockIdx.x * 16;

    const float* xr = x + row0 * INF_;
    for (int i = tid; i < 16 * INF_; i += 256) xs[i] = xr[i];
    __syncthreads();

    {
        float acc[16];
        const float bb = b1[tid];
#pragma unroll
        for (int r = 0; r < 16; ++r) acc[r] = bb;
#pragma unroll 4
        for (int k = 0; k < INF_; ++k) {
            float w = g_W1T[k * F1 + tid];
#pragma unroll
            for (int r = 0; r < 16; ++r) acc[r] = fmaf(xs[r * INF_ + k], w, acc[r]);
        }
#pragma unroll
        for (int r = 0; r < 16; ++r) h1s[r * F1 + tid] = fmaxf(acc[r], 0.f);
    }
    __syncthreads();

    {
        float acc0[16], acc1[16];
        const float bb0 = b2[tid], bb1 = b2[tid + 256];
#pragma unroll
        for (int r = 0; r < 16; ++r) { acc0[r] = bb0; acc1[r] = bb1; }
#pragma unroll 2
        for (int k = 0; k < F1; ++k) {
            float w0 = g_W2T[k * F2 + tid];
            float w1 = g_W2T[k * F2 + tid + 256];
#pragma unroll
            for (int r = 0; r < 16; ++r) {
                float a = h1s[r * F1 + k];
                acc0[r] = fmaf(a, w0, acc0[r]);
                acc1[r] = fmaf(a, w1, acc1[r]);
            }
        }
#pragma unroll
        for (int r = 0; r < 16; ++r) {
            size_t row = row0 + r;
            int b_ = (int)(row / Ln), t_ = (int)(row % Ln);
            float* fp = g_feat + ((size_t)t_ * Bn + b_) * F2;
            fp[tid] = fmaxf(acc0[r], 0.f);
            fp[tid + 256] = fmaxf(acc1[r], 0.f);
        }
    }
}

// ---- xg GEMM (unchanged from R3) ----
template <int K, bool SRC_KMAJOR>
__global__ __launch_bounds__(256, 1) void xg2_kernel(const float* __restrict__ A,
                                                     const float* __restrict__ W4,
                                                     const float* __restrict__ bsum,
                                                     float* __restrict__ out) {
    extern __shared__ float As[];  // [K][36]
    const int tid = threadIdx.x;
    const int row0 = blockIdx.x * 32;

    if (SRC_KMAJOR) {
        const int t = row0 >> 7, b0 = row0 & 127;
        const float* base = A + ((size_t)t * K) * 128 + b0;
        for (int i = tid; i < K * 8; i += 256) {
            int k = i >> 3, r4 = (i & 7) * 4;
            *(float4*)(As + k * 36 + r4) = *(const float4*)(base + (size_t)k * 128 + r4);
        }
    } else {
        constexpr int KQ = K / 4;
        for (int i = tid; i < 32 * KQ; i += 256) {
            int r = i / KQ, kq = i % KQ;
            float4 v = *(const float4*)(A + (size_t)(row0 + r) * K + kq * 4);
            As[(kq * 4 + 0) * 36 + r] = v.x;
            As[(kq * 4 + 1) * 36 + r] = v.y;
            As[(kq * 4 + 2) * 36 + r] = v.z;
            As[(kq * 4 + 3) * 36 + r] = v.w;
        }
    }
    __syncthreads();

    float2 acc[16][4];
#pragma unroll
    for (int p = 0; p < 16; ++p)
#pragma unroll
        for (int g = 0; g < 4; ++g) acc[p][g] = make_float2(0.f, 0.f);

    const float4* wp = (const float4*)W4 + tid;
#pragma unroll 2
    for (int k = 0; k < K; ++k) {
        float4 w4 = wp[(size_t)k * 256];
        float2 w2[4];
        w2[0] = make_float2(w4.x, w4.x);
        w2[1] = make_float2(w4.y, w4.y);
        w2[2] = make_float2(w4.z, w4.z);
        w2[3] = make_float2(w4.w, w4.w);
        const float4* ap = (const float4*)(As + k * 36);
#pragma unroll
        for (int q = 0; q < 8; ++q) {
            float4 a4 = ap[q];
            float2 alo = make_float2(a4.x, a4.y);
            float2 ahi = make_float2(a4.z, a4.w);
#pragma unroll
            for (int g = 0; g < 4; ++g) {
                acc[2 * q][g]     = ffma2(alo, w2[g], acc[2 * q][g]);
                acc[2 * q + 1][g] = ffma2(ahi, w2[g], acc[2 * q + 1][g]);
            }
        }
    }

    float bb[4];
#pragma unroll
    for (int g = 0; g < 4; ++g) bb[g] = bsum[tid + g * 256];
#pragma unroll
    for (int p = 0; p < 16; ++p) {
        float* o0 = out + (size_t)(row0 + 2 * p) * G4 + tid;
        float* o1 = o0 + G4;
#pragma unroll
        for (int g = 0; g < 4; ++g) {
            o0[g * 256] = acc[p][g].x + bb[g];
            o1[g * 256] = acc[p][g].y + bb[g];
        }
    }
}

// ---- LSTM recurrence v3: warp tile 16 rows x 8 cols; k-contiguous w; xg prefetch ----
#define WPITCH 260
template <bool OUT_TBU>
__global__ __launch_bounds__(256) void lstm3_kernel(const float* __restrict__ xg,
                                                    const float* __restrict__ w_hh,
                                                    float* __restrict__ hout) {
    extern __shared__ float sm[];
    float* w_s = sm;                        // [32 cols][260]
    float* h_s = sm + 32 * WPITCH;          // [256 k][32 rows]
    float* gx  = sm + 32 * WPITCH + Hn * 32; // [32 cols][36]

    const int tid = threadIdx.x;
    const int bid = blockIdx.x;
    const int ubase = (bid & 31) * 8;
    const int rbase = (bid >> 5) * 32;
    const int grp = bid >> 5;

    const int w = tid >> 5;
    const int lane = tid & 31;
    const int rq = lane >> 3;                  // row quad 0..3
    const int c = (w >> 1) * 8 + (lane & 7);   // block-local gate col 0..31
    const int r0 = (w & 1) * 16 + rq * 4;      // block-local row 0..28
    const int jcol = (c >> 3) * Hn + ubase + (c & 7);  // global gate col

    // stage w_hh for this block's 32 cols, k-contiguous
    for (int i = tid; i < 32 * Hn; i += 256) {
        int cc = i >> 8, k = i & 255;
        int jc = (cc >> 3) * Hn + ubase + (cc & 7);
        w_s[cc * WPITCH + k] = w_hh[(size_t)jc * Hn + k];
    }

    const int pu = tid >> 5;    // pointwise unit 0..7
    const int pr = tid & 31;    // pointwise row 0..31
    float cst = 0.f;
    unsigned* ctr = &g_grpctr[grp * 32];

    // first-step xg prefetch
    const float* xbase = xg + ((size_t)rbase + r0) * G4 + jcol;
    float x0 = xbase[0];
    float x1 = xbase[G4];
    float x2 = xbase[2 * G4];
    float x3 = xbase[3 * G4];

    __syncthreads();

    for (int t = 0; t < Ln; ++t) {
        const float* hrd = g_hstate[t & 1];
        float* hwr = g_hstate[(t + 1) & 1];

        // stage h[t] (32 rows x 256 k) into smem [k][32]
        for (int i = tid; i < Hn * 8; i += 256) {
            int k = i >> 3, r4 = (i & 7) * 4;
            *(float4*)(h_s + k * 32 + r4) = *(const float4*)(hrd + k * Bn + rbase + r4);
        }
        __syncthreads();

        // gates: 4 rows x 1 col per lane
        float2 a01 = make_float2(0.f, 0.f);
        float2 a23 = make_float2(0.f, 0.f);
        const float* hp = h_s + r0;
        const float* wp = w_s + c * WPITCH;
#pragma unroll 4
        for (int k = 0; k < Hn; k += 4) {
            float4 wv = *(const float4*)(wp + k);
            float4 h0 = *(const float4*)(hp + (k + 0) * 32);
            a01 = ffma2(make_float2(h0.x, h0.y), make_float2(wv.x, wv.x), a01);
            a23 = ffma2(make_float2(h0.z, h0.w), make_float2(wv.x, wv.x), a23);
            float4 h1 = *(const float4*)(hp + (k + 1) * 32);
            a01 = ffma2(make_float2(h1.x, h1.y), make_float2(wv.y, wv.y), a01);
            a23 = ffma2(make_float2(h1.z, h1.w), make_float2(wv.y, wv.y), a23);
            float4 h2 = *(const float4*)(hp + (k + 2) * 32);
            a01 = ffma2(make_float2(h2.x, h2.y), make_float2(wv.z, wv.z), a01);
            a23 = ffma2(make_float2(h2.z, h2.w), make_float2(wv.z, wv.z), a23);
            float4 h3 = *(const float4*)(hp + (k + 3) * 32);
            a01 = ffma2(make_float2(h3.x, h3.y), make_float2(wv.w, wv.w), a01);
            a23 = ffma2(make_float2(h3.z, h3.w), make_float2(wv.w, wv.w), a23);
        }
        a01.x += x0; a01.y += x1; a23.x += x2; a23.y += x3;
        *(float4*)(gx + c * 36 + r0) = make_float4(a01.x, a01.y, a23.x, a23.y);
        __syncthreads();

        // pointwise: thread owns (unit pu, row pr)
        float iv = gx[(0 * 8 + pu) * 36 + pr];
        float fv = gx[(1 * 8 + pu) * 36 + pr];
        float gv = gx[(2 * 8 + pu) * 36 + pr];
        float ov = gx[(3 * 8 + pu) * 36 + pr];
        iv = 1.f / (1.f + expf(-iv));
        fv = 1.f / (1.f + expf(-fv));
        gv = tanhf(gv);
        ov = 1.f / (1.f + expf(-ov));
        cst = fv * cst + iv * gv;
        float hv = ov * tanhf(cst);
        hwr[(ubase + pu) * Bn + rbase + pr] = hv;
        if (OUT_TBU)
            hout[((size_t)t * Bn + rbase + pr) * Hn + ubase + pu] = hv;
        else
            hout[((size_t)t * Hn + ubase + pu) * Bn + rbase + pr] = hv;

        // prefetch next-step xg (independent of barrier)
        if (t + 1 < Ln) {
            const float* xp = xg + (((size_t)(t + 1)) * Bn + rbase + r0) * G4 + jcol;
            x0 = xp[0];
            x1 = xp[G4];
            x2 = xp[2 * G4];
            x3 = xp[3 * G4];
        }

        __syncthreads();   // all h stores done (and prefetch issued)
        if (tid == 0) {
            asm volatile("red.release.gpu.global.add.u32 [%0], %1;" :: "l"(ctr), "r"(1u) : "memory");
            const unsigned target = (unsigned)(t + 1) * 32u;
            unsigned v;
            do {
                asm volatile("ld.acquire.gpu.global.u32 %0, [%1];" : "=r"(v) : "l"(ctr) : "memory");
            } while (v < target);
        }
        __syncthreads();
    }
}

// ---- decision head + ragged mean (hseq is [t][b][u]) ----
__global__ __launch_bounds__(256) void decision_kernel(const float* __restrict__ hseq,
                                                       const float* __restrict__ Wd,
                                                       const float* __restrict__ bd,
                                                       const int* __restrict__ length,
                                                       float* __restrict__ out) {
    const int b = blockIdx.x;
    const int tid = threadIdx.x;
    const int len = length[b];
    const float w = Wd[tid];
    float s0 = 0.f, s1 = 0.f, s2 = 0.f, s3 = 0.f;
    int t = 0;
    for (; t + 4 <= len; t += 4) {
        s0 = fmaf(hseq[((size_t)(t + 0) * Bn + b) * Hn + tid], w, s0);
        s1 = fmaf(hseq[((size_t)(t + 1) * Bn + b) * Hn + tid], w, s1);
        s2 = fmaf(hseq[((size_t)(t + 2) * Bn + b) * Hn + tid], w, s2);
        s3 = fmaf(hseq[((size_t)(t + 3) * Bn + b) * Hn + tid], w, s3);
    }
    for (; t < len; ++t) s0 = fmaf(hseq[((size_t)t * Bn + b) * Hn + tid], w, s0);
    float s = (s0 + s1) + (s2 + s3);
    __shared__ float red[256];
    red[tid] = s;
    __syncthreads();
    for (int st = 128; st > 0; st >>= 1) {
        if (tid < st) red[tid] += red[tid + st];
        __syncthreads();
    }
    if (tid == 0) out[b] = red[0] / (float)len + bd[0];
}

extern "C" void kernel_launch(void* const* d_in, const int* in_sizes, int n_in,
                              void* d_out, int out_size) {
    const float* x     = (const float*)d_in[0];
    const int* length  = (const int*)d_in[1];
    const float* W1    = (const float*)d_in[2];
    const float* b1    = (const float*)d_in[3];
    const float* W2    = (const float*)d_in[4];
    const float* b2    = (const float*)d_in[5];
    const float* w_ih0 = (const float*)d_in[6];
    const float* w_hh0 = (const float*)d_in[7];
    const float* b_ih0 = (const float*)d_in[8];
    const float* b_hh0 = (const float*)d_in[9];
    const float* w_ih1 = (const float*)d_in[10];
    const float* w_hh1 = (const float*)d_in[11];
    const float* b_ih1 = (const float*)d_in[12];
    const float* b_hh1 = (const float*)d_in[13];
    const float* w_ih2 = (const float*)d_in[14];
    const float* w_hh2 = (const float*)d_in[15];
    const float* b_ih2 = (const float*)d_in[16];
    const float* b_hh2 = (const float*)d_in[17];
    const float* Wd    = (const float*)d_in[18];
    const float* bd    = (const float*)d_in[19];
    float* out = (float*)d_out;

    float *dW1T, *dW2T, *dP0, *dP1, *dP2, *dB0, *dB1, *dB2;
    float *dFeat, *dXg, *dHA, *dHB;
    cudaGetSymbolAddress((void**)&dW1T, g_W1T);
    cudaGetSymbolAddress((void**)&dW2T, g_W2T);
    cudaGetSymbolAddress((void**)&dP0, g_W4_0);
    cudaGetSymbolAddress((void**)&dP1, g_W4_1);
    cudaGetSymbolAddress((void**)&dP2, g_W4_2);
    cudaGetSymbolAddress((void**)&dB0, g_bsum0);
    cudaGetSymbolAddress((void**)&dB1, g_bsum1);
    cudaGetSymbolAddress((void**)&dB2, g_bsum2);
    cudaGetSymbolAddress((void**)&dFeat, g_feat);
    cudaGetSymbolAddress((void**)&dXg, g_xg);
    cudaGetSymbolAddress((void**)&dHA, g_hA);
    cudaGetSymbolAddress((void**)&dHB, g_hB);

    const int xg_smem512 = 512 * 36 * sizeof(float);
    const int xg_smem256 = 256 * 36 * sizeof(float);
    const int lstm_smem = (32 * WPITCH + Hn * 32 + 32 * 36) * sizeof(float);
    cudaFuncSetAttribute(xg2_kernel<F2, false>, cudaFuncAttributeMaxDynamicSharedMemorySize, xg_smem512);
    cudaFuncSetAttribute(xg2_kernel<Hn, true>, cudaFuncAttributeMaxDynamicSharedMemorySize, xg_smem256);
    cudaFuncSetAttribute(lstm3_kernel<false>, cudaFuncAttributeMaxDynamicSharedMemorySize, lstm_smem);
    cudaFuncSetAttribute(lstm3_kernel<true>, cudaFuncAttributeMaxDynamicSharedMemorySize, lstm_smem);

    // weight prep
    transpose_kernel<<<(F1 * INF_ + 255) / 256, 256>>>(W1, dW1T, F1, INF_);
    transpose_kernel<<<(F2 * F1 + 255) / 256, 256>>>(W2, dW2T, F2, F1);
    pack_w4_kernel<<<(F2 * G4 + 255) / 256, 256>>>(w_ih0, dP0, F2);
    pack_w4_kernel<<<(Hn * G4 + 255) / 256, 256>>>(w_ih1, dP1, Hn);
    pack_w4_kernel<<<(Hn * G4 + 255) / 256, 256>>>(w_ih2, dP2, Hn);
    addbias_kernel<<<4, 256>>>(b_ih0, b_hh0, dB0, G4);
    addbias_kernel<<<4, 256>>>(b_ih1, b_hh1, dB1, G4);
    addbias_kernel<<<4, 256>>>(b_ih2, b_hh2, dB2, G4);

    const int nrows = Bn * Ln;
    mlp_kernel<<<nrows / 16, 256>>>(x, b1, b2);

    // layer 0
    xg2_kernel<F2, false><<<nrows / 32, 256, xg_smem512>>>(dFeat, dP0, dB0, dXg);
    reset_kernel<<<128, 256>>>();
    lstm3_kernel<false><<<128, 256, lstm_smem>>>(dXg, w_hh0, dHA);
    // layer 1
    xg2_kernel<Hn, true><<<nrows / 32, 256, xg_smem256>>>(dHA, dP1, dB1, dXg);
    reset_kernel<<<128, 256>>>();
    lstm3_kernel<false><<<128, 256, lstm_smem>>>(dXg, w_hh1, dHB);
    // layer 2
    xg2_kernel<Hn, true><<<nrows / 32, 256, xg_smem256>>>(dHB, dP2, dB2, dXg);
    reset_kernel<<<128, 256>>>();
    lstm3_kernel<true><<<128, 256, lstm_smem>>>(dXg, w_hh2, dHA);

    decision_kernel<<<Bn, 256>>>(dHA, Wd, bd, length, out);
}